// round 2
// baseline (speedup 1.0000x reference)
#include <cuda_runtime.h>

// Problem constants
namespace {
constexpr int B = 16, C = 16, P = 512, D = 256;
}

// Scratch (device globals — no allocations allowed)
__device__ float g_S[B * P * D];                 // sum over cycles of aw*query  (8 MB)
__device__ float g_Q[B * C * P * D];             // 134 MB
__device__ float g_K[B * C * P * D];             // 134 MB
__device__ float g_V[B * C * P * D];             // 134 MB
__device__ float g_At[(size_t)B * C * P * P];    // scores / attn (268 MB)

// ---------------------------------------------------------------------------
// Kernel 1: S[b,p,d] = sum_c aw[c,p,d] * query[b,c,p,d]   (vectorized float4)
// ---------------------------------------------------------------------------
__global__ void k_sum(const float* __restrict__ query, const float* __restrict__ aw)
{
    const int PD4 = P * D / 4;
    int i = blockIdx.x * blockDim.x + threadIdx.x;   // over B*P*D/4
    int b = i / PD4;
    int pd = i - b * PD4;
    const float4* q4 = reinterpret_cast<const float4*>(query);
    const float4* a4 = reinterpret_cast<const float4*>(aw);
    float4 acc = make_float4(0.f, 0.f, 0.f, 0.f);
#pragma unroll
    for (int c = 0; c < C; ++c) {
        float4 a = a4[c * PD4 + pd];
        float4 q = q4[(b * C + c) * PD4 + pd];
        acc.x += a.x * q.x; acc.y += a.y * q.y;
        acc.z += a.z * q.z; acc.w += a.w * q.w;
    }
    reinterpret_cast<float4*>(g_S)[i] = acc;
}

// ---------------------------------------------------------------------------
// Kernel 2: per-(b,c) projection GEMMs, 512x256x256.
//   which==0: Q = relu(query @ Wq + bq) * D^-0.5
//   which==1: K = relu(ctx   @ Wk + bk)   ctx built on-the-fly = S - aw*query
//   which==2: V = relu(ctx   @ Wv + bv)
// Tile 64x64, BK=16, 256 threads, 4x4 micro-tile.
// ---------------------------------------------------------------------------
__global__ void k_proj(const float* __restrict__ query, const float* __restrict__ aw,
                       const float* __restrict__ Wq, const float* __restrict__ Wk,
                       const float* __restrict__ Wv, const float* __restrict__ bq,
                       const float* __restrict__ bk, const float* __restrict__ bv)
{
    __shared__ __align__(16) float As[16][64];
    __shared__ __align__(16) float Bs[16][64];

    int z = blockIdx.z;
    int which = z % 3;
    int bc = z / 3;
    int b = bc >> 4, c = bc & 15;
    const float* W    = (which == 0) ? Wq : (which == 1 ? Wk : Wv);
    const float* bias = (which == 0) ? bq : (which == 1 ? bk : bv);
    float* Out        = (which == 0) ? g_Q : (which == 1 ? g_K : g_V);

    int m0 = blockIdx.y * 64;
    int n0 = blockIdx.x * 64;
    int t  = threadIdx.x;
    int tx = t & 15, ty = t >> 4;
    int arow = t >> 2, ac = (t & 3) * 4;
    int brow = t >> 4, bcl = (t & 15) * 4;

    const float* qb = query + (size_t)bc * P * D;
    int pa = m0 + arow;

    float acc[4][4] = {};

    for (int k0 = 0; k0 < D; k0 += 16) {
        float4 av;
        if (which == 0) {
            av = *reinterpret_cast<const float4*>(&qb[pa * D + k0 + ac]);
        } else {
            float4 s = *reinterpret_cast<const float4*>(&g_S[(b * P + pa) * D + k0 + ac]);
            float4 a = *reinterpret_cast<const float4*>(&aw[(c * P + pa) * D + k0 + ac]);
            float4 q = *reinterpret_cast<const float4*>(&qb[pa * D + k0 + ac]);
            av.x = s.x - a.x * q.x; av.y = s.y - a.y * q.y;
            av.z = s.z - a.z * q.z; av.w = s.w - a.w * q.w;
        }
        As[ac + 0][arow] = av.x; As[ac + 1][arow] = av.y;
        As[ac + 2][arow] = av.z; As[ac + 3][arow] = av.w;

        *reinterpret_cast<float4*>(&Bs[brow][bcl]) =
            *reinterpret_cast<const float4*>(&W[c * D * D + (k0 + brow) * D + n0 + bcl]);

        __syncthreads();
#pragma unroll
        for (int k = 0; k < 16; ++k) {
            float4 a4v = *reinterpret_cast<const float4*>(&As[k][ty * 4]);
            float4 b4v = *reinterpret_cast<const float4*>(&Bs[k][tx * 4]);
            float ar[4] = {a4v.x, a4v.y, a4v.z, a4v.w};
            float br[4] = {b4v.x, b4v.y, b4v.z, b4v.w};
#pragma unroll
            for (int i = 0; i < 4; ++i)
#pragma unroll
                for (int j = 0; j < 4; ++j)
                    acc[i][j] += ar[i] * br[j];
        }
        __syncthreads();
    }

    float scale = (which == 0) ? 0.0625f : 1.0f;
    float4 bb = *reinterpret_cast<const float4*>(&bias[c * D + n0 + tx * 4]);
    float bv4[4] = {bb.x, bb.y, bb.z, bb.w};
#pragma unroll
    for (int i = 0; i < 4; ++i) {
        int p = m0 + ty * 4 + i;
        float4 o;
        o.x = fmaxf(acc[i][0] + bv4[0], 0.f) * scale;
        o.y = fmaxf(acc[i][1] + bv4[1], 0.f) * scale;
        o.z = fmaxf(acc[i][2] + bv4[2], 0.f) * scale;
        o.w = fmaxf(acc[i][3] + bv4[3], 0.f) * scale;
        *reinterpret_cast<float4*>(&Out[(size_t)bc * P * D + p * D + n0 + tx * 4]) = o;
    }
}

// ---------------------------------------------------------------------------
// Kernel 3: scores[b,c,p,q] = sum_e Q[p,e]*K[q,e]    (NT GEMM 512x512x256)
// ---------------------------------------------------------------------------
__global__ void k_scores()
{
    __shared__ __align__(16) float As[16][64];
    __shared__ __align__(16) float Bs[16][64];
    int bc = blockIdx.z;
    int m0 = blockIdx.y * 64, n0 = blockIdx.x * 64;
    const float* Qb = g_Q + (size_t)bc * P * D;
    const float* Kb = g_K + (size_t)bc * P * D;
    int t = threadIdx.x;
    int tx = t & 15, ty = t >> 4;
    int arow = t >> 2, ac = (t & 3) * 4;

    float acc[4][4] = {};
    for (int k0 = 0; k0 < D; k0 += 16) {
        float4 a = *reinterpret_cast<const float4*>(&Qb[(m0 + arow) * D + k0 + ac]);
        As[ac + 0][arow] = a.x; As[ac + 1][arow] = a.y;
        As[ac + 2][arow] = a.z; As[ac + 3][arow] = a.w;
        float4 b4 = *reinterpret_cast<const float4*>(&Kb[(n0 + arow) * D + k0 + ac]);
        Bs[ac + 0][arow] = b4.x; Bs[ac + 1][arow] = b4.y;
        Bs[ac + 2][arow] = b4.z; Bs[ac + 3][arow] = b4.w;
        __syncthreads();
#pragma unroll
        for (int k = 0; k < 16; ++k) {
            float4 a4v = *reinterpret_cast<const float4*>(&As[k][ty * 4]);
            float4 b4v = *reinterpret_cast<const float4*>(&Bs[k][tx * 4]);
            float ar[4] = {a4v.x, a4v.y, a4v.z, a4v.w};
            float br[4] = {b4v.x, b4v.y, b4v.z, b4v.w};
#pragma unroll
            for (int i = 0; i < 4; ++i)
#pragma unroll
                for (int j = 0; j < 4; ++j)
                    acc[i][j] += ar[i] * br[j];
        }
        __syncthreads();
    }
#pragma unroll
    for (int i = 0; i < 4; ++i) {
        int p = m0 + ty * 4 + i;
        float4 o = make_float4(acc[i][0], acc[i][1], acc[i][2], acc[i][3]);
        *reinterpret_cast<float4*>(&g_At[(size_t)bc * P * P + (size_t)p * P + n0 + tx * 4]) = o;
    }
}

// ---------------------------------------------------------------------------
// Kernel 4: row softmax over last axis (512). One block (128 thr) per row.
// ---------------------------------------------------------------------------
__global__ void k_softmax()
{
    size_t row = blockIdx.x;          // over B*C*P
    int t = threadIdx.x;              // 128 threads, 4 floats each
    float4* r = reinterpret_cast<float4*>(g_At + row * P);
    float4 v = r[t];
    float m = fmaxf(fmaxf(v.x, v.y), fmaxf(v.z, v.w));
#pragma unroll
    for (int o = 16; o > 0; o >>= 1) m = fmaxf(m, __shfl_xor_sync(0xffffffffu, m, o));
    __shared__ float sm[4], ss[4];
    int w = t >> 5, lane = t & 31;
    if (lane == 0) sm[w] = m;
    __syncthreads();
    m = fmaxf(fmaxf(sm[0], sm[1]), fmaxf(sm[2], sm[3]));
    v.x = __expf(v.x - m); v.y = __expf(v.y - m);
    v.z = __expf(v.z - m); v.w = __expf(v.w - m);
    float s = v.x + v.y + v.z + v.w;
#pragma unroll
    for (int o = 16; o > 0; o >>= 1) s += __shfl_xor_sync(0xffffffffu, s, o);
    if (lane == 0) ss[w] = s;
    __syncthreads();
    s = ss[0] + ss[1] + ss[2] + ss[3];
    float inv = 1.0f / s;
    v.x *= inv; v.y *= inv; v.z *= inv; v.w *= inv;
    r[t] = v;
}

// ---------------------------------------------------------------------------
// Kernel 5: out[b,c,p,e] = sum_q attn[p,q]*V[q,e]    (NN GEMM 512x256x512)
// ---------------------------------------------------------------------------
__global__ void k_av(float* __restrict__ out)
{
    __shared__ __align__(16) float As[16][64];
    __shared__ __align__(16) float Bs[16][64];
    int bc = blockIdx.z;
    int m0 = blockIdx.y * 64, n0 = blockIdx.x * 64;
    const float* Ab = g_At + (size_t)bc * P * P;
    const float* Vb = g_V + (size_t)bc * P * D;
    int t = threadIdx.x;
    int tx = t & 15, ty = t >> 4;
    int arow = t >> 2, ac = (t & 3) * 4;
    int brow = t >> 4, bcl = (t & 15) * 4;

    float acc[4][4] = {};
    for (int k0 = 0; k0 < P; k0 += 16) {
        float4 a = *reinterpret_cast<const float4*>(&Ab[(size_t)(m0 + arow) * P + k0 + ac]);
        As[ac + 0][arow] = a.x; As[ac + 1][arow] = a.y;
        As[ac + 2][arow] = a.z; As[ac + 3][arow] = a.w;
        *reinterpret_cast<float4*>(&Bs[brow][bcl]) =
            *reinterpret_cast<const float4*>(&Vb[(k0 + brow) * D + n0 + bcl]);
        __syncthreads();
#pragma unroll
        for (int k = 0; k < 16; ++k) {
            float4 a4v = *reinterpret_cast<const float4*>(&As[k][ty * 4]);
            float4 b4v = *reinterpret_cast<const float4*>(&Bs[k][tx * 4]);
            float ar[4] = {a4v.x, a4v.y, a4v.z, a4v.w};
            float br[4] = {b4v.x, b4v.y, b4v.z, b4v.w};
#pragma unroll
            for (int i = 0; i < 4; ++i)
#pragma unroll
                for (int j = 0; j < 4; ++j)
                    acc[i][j] += ar[i] * br[j];
        }
        __syncthreads();
    }
#pragma unroll
    for (int i = 0; i < 4; ++i) {
        int p = m0 + ty * 4 + i;
        float4 o = make_float4(acc[i][0], acc[i][1], acc[i][2], acc[i][3]);
        *reinterpret_cast<float4*>(&out[(size_t)bc * P * D + p * D + n0 + tx * 4]) = o;
    }
}

// ---------------------------------------------------------------------------
extern "C" void kernel_launch(void* const* d_in, const int* /*in_sizes*/, int /*n_in*/,
                              void* d_out, int /*out_size*/)
{
    const float* query = (const float*)d_in[0];
    const float* aw    = (const float*)d_in[1];
    const float* Wq    = (const float*)d_in[2];
    const float* Wk    = (const float*)d_in[3];
    const float* Wv    = (const float*)d_in[4];
    const float* bq    = (const float*)d_in[5];
    const float* bk    = (const float*)d_in[6];
    const float* bv    = (const float*)d_in[7];
    float* out = (float*)d_out;

    k_sum<<<(B * P * D / 4) / 256, 256>>>(query, aw);
    k_proj<<<dim3(D / 64, P / 64, B * C * 3), 256>>>(query, aw, Wq, Wk, Wv, bq, bk, bv);
    k_scores<<<dim3(P / 64, P / 64, B * C), 256>>>();
    k_softmax<<<B * C * P, 128>>>();
    k_av<<<dim3(D / 64, P / 64, B * C), 256>>>(out);
}

// round 3
// speedup vs baseline: 1.9221x; 1.9221x over previous
#include <cuda_runtime.h>
#include <cuda_bf16.h>
#include <cstdint>

namespace {
constexpr int B = 16, C = 16, P = 512, D = 256;
constexpr int BM = 128, BN = 128, BKF = 32;   // fp32-K per stage
constexpr int SK = 72;                        // smem row stride in halves (64 data + 8 pad)
}

// ---------------- device-global scratch (no allocations allowed) -------------
__device__ float g_S[B * P * D];                                   // 8 MB
__device__ __nv_bfloat16 g_qh[(size_t)B * C * P * D];              // 67 MB each
__device__ __nv_bfloat16 g_ql[(size_t)B * C * P * D];
__device__ __nv_bfloat16 g_ch[(size_t)B * C * P * D];
__device__ __nv_bfloat16 g_cl[(size_t)B * C * P * D];
__device__ __nv_bfloat16 g_wh[(size_t)3 * C * D * D];
__device__ __nv_bfloat16 g_wl[(size_t)3 * C * D * D];
__device__ __nv_bfloat16 g_Qh[(size_t)B * C * P * D];
__device__ __nv_bfloat16 g_Ql[(size_t)B * C * P * D];
__device__ __nv_bfloat16 g_Kh[(size_t)B * C * P * D];
__device__ __nv_bfloat16 g_Kl[(size_t)B * C * P * D];
__device__ __nv_bfloat16 g_Vh[(size_t)B * C * P * D];
__device__ __nv_bfloat16 g_Vl[(size_t)B * C * P * D];
__device__ float g_At[(size_t)B * C * P * P];                      // 268 MB
__device__ __nv_bfloat16 g_Ah[(size_t)B * C * P * P];              // 134 MB each
__device__ __nv_bfloat16 g_Al[(size_t)B * C * P * P];

// ---------------- helpers ----------------------------------------------------
__device__ __forceinline__ uint32_t smem_u32(const void* p) {
    return (uint32_t)__cvta_generic_to_shared(p);
}
__device__ __forceinline__ void ldsm_x4(uint32_t& r0, uint32_t& r1, uint32_t& r2,
                                        uint32_t& r3, uint32_t a) {
    asm volatile("ldmatrix.sync.aligned.m8n8.x4.shared.b16 {%0,%1,%2,%3}, [%4];"
                 : "=r"(r0), "=r"(r1), "=r"(r2), "=r"(r3) : "r"(a));
}
__device__ __forceinline__ void mma_bf16(float* c, const uint32_t* a, const uint32_t* b) {
    asm volatile(
        "mma.sync.aligned.m16n8k16.row.col.f32.bf16.bf16.f32 "
        "{%0,%1,%2,%3}, {%4,%5,%6,%7}, {%8,%9}, {%0,%1,%2,%3};"
        : "+f"(c[0]), "+f"(c[1]), "+f"(c[2]), "+f"(c[3])
        : "r"(a[0]), "r"(a[1]), "r"(a[2]), "r"(a[3]), "r"(b[0]), "r"(b[1]));
}
__device__ __forceinline__ void split1(float x, __nv_bfloat16& h, __nv_bfloat16& l) {
    h = __float2bfloat16(x);
    l = __float2bfloat16(x - __bfloat162float(h));
}
__device__ __forceinline__ void split_store2(__nv_bfloat16* H, __nv_bfloat16* L,
                                             size_t off, float x, float y) {
    __nv_bfloat16 hx, lx, hy, ly;
    split1(x, hx, lx); split1(y, hy, ly);
    *reinterpret_cast<__nv_bfloat162*>(H + off) = __halves2bfloat162(hx, hy);
    *reinterpret_cast<__nv_bfloat162*>(L + off) = __halves2bfloat162(lx, ly);
}

// Direct tile load: 128 rows x 32 halves from hi/lo bf16 arrays into smem
// (hi at cols 0..31, lo at cols 32..63 of each SK-row).
__device__ __forceinline__ void tile_direct(__nv_bfloat16* dst,
                                            const __nv_bfloat16* __restrict__ srcH,
                                            const __nv_bfloat16* __restrict__ srcL,
                                            int ld, int row0, int k0, int t) {
#pragma unroll
    for (int i = t; i < 1024; i += 256) {
        int row = i >> 3;
        int kk = (i & 7) * 4;
        size_t s = (size_t)(row0 + row) * ld + k0 + kk;
        uint2 vh = *reinterpret_cast<const uint2*>(srcH + s);
        uint2 vl = *reinterpret_cast<const uint2*>(srcL + s);
        *reinterpret_cast<uint2*>(&dst[row * SK + kk])      = vh;
        *reinterpret_cast<uint2*>(&dst[row * SK + 32 + kk]) = vl;
    }
}

// Transposed tile load: source [k][n] (n contiguous, row stride ldn) -> smem [n][k].
// Tile: k0..k0+31 rows, n0..n0+127 cols.
__device__ __forceinline__ void tile_trans(__nv_bfloat16* dst,
                                           const __nv_bfloat16* __restrict__ srcH,
                                           const __nv_bfloat16* __restrict__ srcL,
                                           int ldn, int k0, int n0, int t) {
    int krow = t & 31;
    int ng = t >> 5;   // warp id 0..7
#pragma unroll
    for (int i = 0; i < 4; ++i) {
        int n4 = ng * 16 + i * 4;
        size_t s = (size_t)(k0 + krow) * ldn + n0 + n4;
        uint2 vh = *reinterpret_cast<const uint2*>(srcH + s);
        uint2 vl = *reinterpret_cast<const uint2*>(srcL + s);
        const __nv_bfloat16* hh = reinterpret_cast<const __nv_bfloat16*>(&vh);
        const __nv_bfloat16* ll = reinterpret_cast<const __nv_bfloat16*>(&vl);
#pragma unroll
        for (int e = 0; e < 4; ++e) {
            dst[(n4 + e) * SK + krow]      = hh[e];
            dst[(n4 + e) * SK + 32 + krow] = ll[e];
        }
    }
}

// Warp-tile compute over one loaded stage (2 k16-steps, 3-MMA hi/lo split).
__device__ __forceinline__ void stage_compute(const __nv_bfloat16* As,
                                              const __nv_bfloat16* Bs,
                                              float acc[2][8][4], int lane, int wid) {
    int wm = (wid >> 1) * 32;
    int wn = (wid & 1) * 64;
    int lr = lane & 7, lm = lane >> 3;
    int a_row = (lm & 1) * 8 + lr;
    int a_col = (lm >> 1) * 8;
    int b_row = (lm >> 1) * 8 + lr;
    int b_col = (lm & 1) * 8;
#pragma unroll
    for (int ks = 0; ks < 2; ++ks) {
        int k0 = ks * 16;
        uint32_t Ah[2][4], Al[2][4], Bh[8][2], Bl[8][2];
#pragma unroll
        for (int mt = 0; mt < 2; ++mt) {
            uint32_t a = smem_u32(&As[(wm + mt * 16 + a_row) * SK + k0 + a_col]);
            ldsm_x4(Ah[mt][0], Ah[mt][1], Ah[mt][2], Ah[mt][3], a);
            uint32_t al = smem_u32(&As[(wm + mt * 16 + a_row) * SK + 32 + k0 + a_col]);
            ldsm_x4(Al[mt][0], Al[mt][1], Al[mt][2], Al[mt][3], al);
        }
#pragma unroll
        for (int jp = 0; jp < 4; ++jp) {
            uint32_t b = smem_u32(&Bs[(wn + jp * 16 + b_row) * SK + k0 + b_col]);
            ldsm_x4(Bh[2 * jp][0], Bh[2 * jp][1], Bh[2 * jp + 1][0], Bh[2 * jp + 1][1], b);
            uint32_t bl = smem_u32(&Bs[(wn + jp * 16 + b_row) * SK + 32 + k0 + b_col]);
            ldsm_x4(Bl[2 * jp][0], Bl[2 * jp][1], Bl[2 * jp + 1][0], Bl[2 * jp + 1][1], bl);
        }
#pragma unroll
        for (int mt = 0; mt < 2; ++mt)
#pragma unroll
            for (int nt = 0; nt < 8; ++nt) {
                mma_bf16(acc[mt][nt], Ah[mt], Bh[nt]);
                mma_bf16(acc[mt][nt], Ah[mt], Bl[nt]);
                mma_bf16(acc[mt][nt], Al[mt], Bh[nt]);
            }
    }
}

// ---------------------------------------------------------------------------
// Kernel 1: S[b,p,d] = sum_c aw[c,p,d]*query[b,c,p,d]
// ---------------------------------------------------------------------------
__global__ void k_sum(const float* __restrict__ query, const float* __restrict__ aw)
{
    const int PD4 = P * D / 4;
    int i = blockIdx.x * blockDim.x + threadIdx.x;
    int b = i / PD4;
    int pd = i - b * PD4;
    const float4* q4 = reinterpret_cast<const float4*>(query);
    const float4* a4 = reinterpret_cast<const float4*>(aw);
    float4 acc = make_float4(0.f, 0.f, 0.f, 0.f);
#pragma unroll
    for (int c = 0; c < C; ++c) {
        float4 a = a4[c * PD4 + pd];
        float4 q = q4[(b * C + c) * PD4 + pd];
        acc.x += a.x * q.x; acc.y += a.y * q.y;
        acc.z += a.z * q.z; acc.w += a.w * q.w;
    }
    reinterpret_cast<float4*>(g_S)[i] = acc;
}

// ---------------------------------------------------------------------------
// Kernel 2: split query and context (= S - aw*query) into bf16 hi/lo
// ---------------------------------------------------------------------------
__global__ void k_prep(const float* __restrict__ query, const float* __restrict__ aw)
{
    const int PD4 = P * D / 4, CPD4 = C * PD4;
    int i = blockIdx.x * blockDim.x + threadIdx.x;   // over B*C*P*D/4
    int b = i / CPD4;
    int r = i - b * CPD4;
    int c = r / PD4;
    int pd4 = r - c * PD4;
    float4 q = reinterpret_cast<const float4*>(query)[i];
    float4 a = reinterpret_cast<const float4*>(aw)[c * PD4 + pd4];
    float4 s = reinterpret_cast<const float4*>(g_S)[b * PD4 + pd4];
    float4 ctx;
    ctx.x = s.x - a.x * q.x; ctx.y = s.y - a.y * q.y;
    ctx.z = s.z - a.z * q.z; ctx.w = s.w - a.w * q.w;
    size_t off = (size_t)i * 4;
    split_store2(g_qh, g_ql, off,     q.x, q.y);
    split_store2(g_qh, g_ql, off + 2, q.z, q.w);
    split_store2(g_ch, g_cl, off,     ctx.x, ctx.y);
    split_store2(g_ch, g_cl, off + 2, ctx.z, ctx.w);
}

__global__ void k_prep_w(const float* __restrict__ Wq, const float* __restrict__ Wk,
                         const float* __restrict__ Wv)
{
    const int CDD4 = C * D * D / 4;
    int i = blockIdx.x * blockDim.x + threadIdx.x;   // over 3*C*D*D/4
    int which = i / CDD4;
    int j = i - which * CDD4;
    const float4* W = (which == 0) ? reinterpret_cast<const float4*>(Wq)
                   : (which == 1) ? reinterpret_cast<const float4*>(Wk)
                                  : reinterpret_cast<const float4*>(Wv);
    float4 v = W[j];
    size_t off = (size_t)i * 4;
    split_store2(g_wh, g_wl, off,     v.x, v.y);
    split_store2(g_wh, g_wl, off + 2, v.z, v.w);
}

// ---------------------------------------------------------------------------
// Kernel 3: projection GEMMs (512x256x256) -> relu(+bias) [*scale], split bf16
// ---------------------------------------------------------------------------
__global__ void __launch_bounds__(256) k_proj_t(
    const float* __restrict__ bq, const float* __restrict__ bk,
    const float* __restrict__ bv)
{
    __shared__ __align__(128) __nv_bfloat16 As[BM * SK];
    __shared__ __align__(128) __nv_bfloat16 Bs[BN * SK];

    int z = blockIdx.z;
    int which = z % 3;
    int bc = z / 3;
    int c = bc & 15;
    const __nv_bfloat16* AH = ((which == 0) ? g_qh : g_ch) + (size_t)bc * P * D;
    const __nv_bfloat16* AL = ((which == 0) ? g_ql : g_cl) + (size_t)bc * P * D;
    const __nv_bfloat16* WH = g_wh + ((size_t)which * C + c) * D * D;
    const __nv_bfloat16* WL = g_wl + ((size_t)which * C + c) * D * D;
    const float* bias = (which == 0) ? bq : (which == 1 ? bk : bv);
    __nv_bfloat16* OH = (which == 0) ? g_Qh : (which == 1 ? g_Kh : g_Vh);
    __nv_bfloat16* OL = (which == 0) ? g_Ql : (which == 1 ? g_Kl : g_Vl);

    int bm0 = blockIdx.y * BM, bn0 = blockIdx.x * BN;
    int t = threadIdx.x, lane = t & 31, wid = t >> 5;
    float acc[2][8][4] = {};

    for (int k0 = 0; k0 < D; k0 += BKF) {
        tile_direct(As, AH, AL, D, bm0, k0, t);
        tile_trans(Bs, WH, WL, D, k0, bn0, t);
        __syncthreads();
        stage_compute(As, Bs, acc, lane, wid);
        __syncthreads();
    }

    float scale = (which == 0) ? 0.0625f : 1.0f;   // D^-0.5 for Q
    int wm = (wid >> 1) * 32, wn = (wid & 1) * 64;
    int gr = lane >> 2, gc = (lane & 3) * 2;
#pragma unroll
    for (int mt = 0; mt < 2; ++mt)
#pragma unroll
        for (int nt = 0; nt < 8; ++nt) {
            int p0 = bm0 + wm + mt * 16 + gr;
            int e0 = bn0 + wn + nt * 8 + gc;
            float2 bb = *reinterpret_cast<const float2*>(&bias[c * D + e0]);
            float v0 = fmaxf(acc[mt][nt][0] + bb.x, 0.f) * scale;
            float v1 = fmaxf(acc[mt][nt][1] + bb.y, 0.f) * scale;
            float v2 = fmaxf(acc[mt][nt][2] + bb.x, 0.f) * scale;
            float v3 = fmaxf(acc[mt][nt][3] + bb.y, 0.f) * scale;
            size_t base = (size_t)bc * P * D;
            split_store2(OH, OL, base + (size_t)p0 * D + e0, v0, v1);
            split_store2(OH, OL, base + (size_t)(p0 + 8) * D + e0, v2, v3);
        }
}

// ---------------------------------------------------------------------------
// Kernel 4: scores = Q @ K^T (512x512x256), fp32 out
// ---------------------------------------------------------------------------
__global__ void __launch_bounds__(256) k_scores_t()
{
    __shared__ __align__(128) __nv_bfloat16 As[BM * SK];
    __shared__ __align__(128) __nv_bfloat16 Bs[BN * SK];

    int bc = blockIdx.z;
    size_t base = (size_t)bc * P * D;
    int bm0 = blockIdx.y * BM, bn0 = blockIdx.x * BN;
    int t = threadIdx.x, lane = t & 31, wid = t >> 5;
    float acc[2][8][4] = {};

    for (int k0 = 0; k0 < D; k0 += BKF) {
        tile_direct(As, g_Qh + base, g_Ql + base, D, bm0, k0, t);
        tile_direct(Bs, g_Kh + base, g_Kl + base, D, bn0, k0, t);
        __syncthreads();
        stage_compute(As, Bs, acc, lane, wid);
        __syncthreads();
    }

    int wm = (wid >> 1) * 32, wn = (wid & 1) * 64;
    int gr = lane >> 2, gc = (lane & 3) * 2;
    float* Out = g_At + (size_t)bc * P * P;
#pragma unroll
    for (int mt = 0; mt < 2; ++mt)
#pragma unroll
        for (int nt = 0; nt < 8; ++nt) {
            int p0 = bm0 + wm + mt * 16 + gr;
            int q0 = bn0 + wn + nt * 8 + gc;
            *reinterpret_cast<float2*>(&Out[(size_t)p0 * P + q0]) =
                make_float2(acc[mt][nt][0], acc[mt][nt][1]);
            *reinterpret_cast<float2*>(&Out[(size_t)(p0 + 8) * P + q0]) =
                make_float2(acc[mt][nt][2], acc[mt][nt][3]);
        }
}

// ---------------------------------------------------------------------------
// Kernel 5: row softmax (512) + split to bf16 hi/lo
// ---------------------------------------------------------------------------
__global__ void k_softmax_t()
{
    size_t row = blockIdx.x;
    int t = threadIdx.x;
    const float4* r = reinterpret_cast<const float4*>(g_At + row * P);
    float4 v = r[t];
    float m = fmaxf(fmaxf(v.x, v.y), fmaxf(v.z, v.w));
#pragma unroll
    for (int o = 16; o > 0; o >>= 1) m = fmaxf(m, __shfl_xor_sync(0xffffffffu, m, o));
    __shared__ float sm[4], ss[4];
    int w = t >> 5, lane = t & 31;
    if (lane == 0) sm[w] = m;
    __syncthreads();
    m = fmaxf(fmaxf(sm[0], sm[1]), fmaxf(sm[2], sm[3]));
    v.x = __expf(v.x - m); v.y = __expf(v.y - m);
    v.z = __expf(v.z - m); v.w = __expf(v.w - m);
    float s = v.x + v.y + v.z + v.w;
#pragma unroll
    for (int o = 16; o > 0; o >>= 1) s += __shfl_xor_sync(0xffffffffu, s, o);
    if (lane == 0) ss[w] = s;
    __syncthreads();
    s = ss[0] + ss[1] + ss[2] + ss[3];
    float inv = 1.0f / s;
    size_t off = row * P + (size_t)t * 4;
    split_store2(g_Ah, g_Al, off,     v.x * inv, v.y * inv);
    split_store2(g_Ah, g_Al, off + 2, v.z * inv, v.w * inv);
}

// ---------------------------------------------------------------------------
// Kernel 6: out = attn @ V (512x256x512), fp32 out
// ---------------------------------------------------------------------------
__global__ void __launch_bounds__(256) k_av_t(float* __restrict__ out)
{
    __shared__ __align__(128) __nv_bfloat16 As[BM * SK];
    __shared__ __align__(128) __nv_bfloat16 Bs[BN * SK];

    int bc = blockIdx.z;
    const __nv_bfloat16* AH = g_Ah + (size_t)bc * P * P;
    const __nv_bfloat16* AL = g_Al + (size_t)bc * P * P;
    const __nv_bfloat16* VH = g_Vh + (size_t)bc * P * D;
    const __nv_bfloat16* VL = g_Vl + (size_t)bc * P * D;
    int bm0 = blockIdx.y * BM, bn0 = blockIdx.x * BN;
    int t = threadIdx.x, lane = t & 31, wid = t >> 5;
    float acc[2][8][4] = {};

    for (int k0 = 0; k0 < P; k0 += BKF) {
        tile_direct(As, AH, AL, P, bm0, k0, t);
        tile_trans(Bs, VH, VL, D, k0, bn0, t);
        __syncthreads();
        stage_compute(As, Bs, acc, lane, wid);
        __syncthreads();
    }

    int wm = (wid >> 1) * 32, wn = (wid & 1) * 64;
    int gr = lane >> 2, gc = (lane & 3) * 2;
    float* Ob = out + (size_t)bc * P * D;
#pragma unroll
    for (int mt = 0; mt < 2; ++mt)
#pragma unroll
        for (int nt = 0; nt < 8; ++nt) {
            int p0 = bm0 + wm + mt * 16 + gr;
            int e0 = bn0 + wn + nt * 8 + gc;
            *reinterpret_cast<float2*>(&Ob[(size_t)p0 * D + e0]) =
                make_float2(acc[mt][nt][0], acc[mt][nt][1]);
            *reinterpret_cast<float2*>(&Ob[(size_t)(p0 + 8) * D + e0]) =
                make_float2(acc[mt][nt][2], acc[mt][nt][3]);
        }
}

// ---------------------------------------------------------------------------
extern "C" void kernel_launch(void* const* d_in, const int* /*in_sizes*/, int /*n_in*/,
                              void* d_out, int /*out_size*/)
{
    const float* query = (const float*)d_in[0];
    const float* aw    = (const float*)d_in[1];
    const float* Wq    = (const float*)d_in[2];
    const float* Wk    = (const float*)d_in[3];
    const float* Wv    = (const float*)d_in[4];
    const float* bq    = (const float*)d_in[5];
    const float* bk    = (const float*)d_in[6];
    const float* bv    = (const float*)d_in[7];
    float* out = (float*)d_out;

    k_sum<<<(B * P * D / 4) / 256, 256>>>(query, aw);
    k_prep<<<(B * C * P * D / 4) / 256, 256>>>(query, aw);
    k_prep_w<<<(3 * C * D * D / 4) / 256, 256>>>(Wq, Wk, Wv);
    k_proj_t<<<dim3(D / BN, P / BM, B * C * 3), 256>>>(bq, bk, bv);
    k_scores_t<<<dim3(P / BN, P / BM, B * C), 256>>>();
    k_softmax_t<<<B * C * P, 128>>>();
    k_av_t<<<dim3(D / BN, P / BM, B * C), 256>>>(out);
}

// round 8
// speedup vs baseline: 2.8365x; 1.4757x over previous
#include <cuda_runtime.h>
#include <cuda_bf16.h>
#include <cstdint>
#include <cstring>

// ============================================================================
// Problem constants / tiling (legacy mma.sync path — tcgen05 not available
// under the harness's compute_103 virtual arch)
// ============================================================================
namespace {
constexpr int B = 16, C = 16, P = 512, D = 256;
constexpr int BM = 128, BN = 128, BKF = 32;      // CTA tile, fp32-K per stage
constexpr int SK = 72;                            // smem row stride in halves
constexpr int TILE_HALVES = 128 * SK;             // one operand tile (hi+lo)
constexpr int STAGE_BYTES = 2 * TILE_HALVES * 2;  // A+B tile = 36864 B
constexpr int DYN_BYTES = 2 * STAGE_BYTES;        // double buffer = 73728 B
}

// ============================================================================
// Device-global scratch (no allocations allowed)
// ============================================================================
__device__ __nv_bfloat16 g_qh[(size_t)B * C * P * D];
__device__ __nv_bfloat16 g_ql[(size_t)B * C * P * D];
__device__ __nv_bfloat16 g_ch[(size_t)B * C * P * D];
__device__ __nv_bfloat16 g_cl[(size_t)B * C * P * D];
__device__ __nv_bfloat16 g_wth[(size_t)3 * C * D * D];   // W^T hi  [e][d]
__device__ __nv_bfloat16 g_wtl[(size_t)3 * C * D * D];   // W^T lo
__device__ __nv_bfloat16 g_Qh[(size_t)B * C * P * D];
__device__ __nv_bfloat16 g_Ql[(size_t)B * C * P * D];
__device__ __nv_bfloat16 g_Kh[(size_t)B * C * P * D];
__device__ __nv_bfloat16 g_Kl[(size_t)B * C * P * D];
__device__ __nv_bfloat16 g_VTh[(size_t)B * C * D * P];   // V^T [e][p]
__device__ __nv_bfloat16 g_VTl[(size_t)B * C * D * P];
__device__ float g_At[(size_t)B * C * P * P];            // scores fp32
__device__ __nv_bfloat16 g_Ah[(size_t)B * C * P * P];    // attn hi
__device__ __nv_bfloat16 g_Al[(size_t)B * C * P * P];    // attn lo

// ============================================================================
// Helpers
// ============================================================================
__device__ __forceinline__ uint32_t smem_u32(const void* p) {
    return (uint32_t)__cvta_generic_to_shared(p);
}
__device__ __forceinline__ void ldsm_x4(uint32_t& r0, uint32_t& r1, uint32_t& r2,
                                        uint32_t& r3, uint32_t a) {
    asm volatile("ldmatrix.sync.aligned.m8n8.x4.shared.b16 {%0,%1,%2,%3}, [%4];"
                 : "=r"(r0), "=r"(r1), "=r"(r2), "=r"(r3) : "r"(a));
}
__device__ __forceinline__ void mma_bf16(float* c, const uint32_t* a, const uint32_t* b) {
    asm volatile(
        "mma.sync.aligned.m16n8k16.row.col.f32.bf16.bf16.f32 "
        "{%0,%1,%2,%3}, {%4,%5,%6,%7}, {%8,%9}, {%0,%1,%2,%3};"
        : "+f"(c[0]), "+f"(c[1]), "+f"(c[2]), "+f"(c[3])
        : "r"(a[0]), "r"(a[1]), "r"(a[2]), "r"(a[3]), "r"(b[0]), "r"(b[1]));
}
__device__ __forceinline__ void cp16(uint32_t dst, const void* src) {
    asm volatile("cp.async.cg.shared.global [%0], [%1], 16;" :: "r"(dst), "l"(src));
}
#define CP_COMMIT() asm volatile("cp.async.commit_group;" ::: "memory")
#define CP_WAIT_1() asm volatile("cp.async.wait_group 1;" ::: "memory")
#define CP_WAIT_0() asm volatile("cp.async.wait_group 0;" ::: "memory")

__device__ __forceinline__ void split1(float x, __nv_bfloat16& h, __nv_bfloat16& l) {
    h = __float2bfloat16(x);
    l = __float2bfloat16(x - __bfloat162float(h));
}
__device__ __forceinline__ void split_store2(__nv_bfloat16* H, __nv_bfloat16* L,
                                             size_t off, float x, float y) {
    __nv_bfloat16 hx, lx, hy, ly;
    split1(x, hx, lx); split1(y, hy, ly);
    *reinterpret_cast<__nv_bfloat162*>(H + off) = __halves2bfloat162(hx, hy);
    *reinterpret_cast<__nv_bfloat162*>(L + off) = __halves2bfloat162(lx, ly);
}

// ============================================================================
// Async stage fill: A[128x32] + B[128x32] hi/lo (K-major) -> padded smem
// ============================================================================
__device__ __forceinline__ void fill_stage(char* buf,
    const __nv_bfloat16* __restrict__ Ah, const __nv_bfloat16* __restrict__ Al,
    int lda, int m0,
    const __nv_bfloat16* __restrict__ Bh, const __nv_bfloat16* __restrict__ Bl,
    int ldb, int n0, int k0, int t)
{
    uint32_t ab = smem_u32(buf);
    uint32_t bb = ab + TILE_HALVES * 2;
#pragma unroll
    for (int i = t; i < 512; i += 128) {
        int r = i >> 2, ch = (i & 3) * 8;
        size_t sa = (size_t)(m0 + r) * lda + k0 + ch;
        cp16(ab + (r * SK + ch) * 2,      Ah + sa);
        cp16(ab + (r * SK + 32 + ch) * 2, Al + sa);
        size_t sb = (size_t)(n0 + r) * ldb + k0 + ch;
        cp16(bb + (r * SK + ch) * 2,      Bh + sb);
        cp16(bb + (r * SK + 32 + ch) * 2, Bl + sb);
    }
    CP_COMMIT();
}

// ============================================================================
// One-stage compute: 64x64 warp tile, 2 k16 steps, 3-MMA hi/lo split
// ============================================================================
__device__ __forceinline__ void compute_stage(const __nv_bfloat16* As,
                                              const __nv_bfloat16* Bs,
                                              float acc[4][8][4], int lane, int wid)
{
    int wm = (wid & 1) * 64;
    int wn = (wid >> 1) * 64;
    int lr = lane & 7, lm = lane >> 3;
    int a_row = (lm & 1) * 8 + lr;
    int a_col = (lm >> 1) * 8;
    int b_row = (lm >> 1) * 8 + lr;
    int b_col = (lm & 1) * 8;
#pragma unroll
    for (int ks = 0; ks < 2; ++ks) {
        int k0 = ks * 16;
        uint32_t Ahf[4][4], Alf[4][4];
#pragma unroll
        for (int mt = 0; mt < 4; ++mt) {
            uint32_t a = smem_u32(&As[(wm + mt * 16 + a_row) * SK + k0 + a_col]);
            ldsm_x4(Ahf[mt][0], Ahf[mt][1], Ahf[mt][2], Ahf[mt][3], a);
            uint32_t al = smem_u32(&As[(wm + mt * 16 + a_row) * SK + 32 + k0 + a_col]);
            ldsm_x4(Alf[mt][0], Alf[mt][1], Alf[mt][2], Alf[mt][3], al);
        }
#pragma unroll
        for (int h = 0; h < 2; ++h) {
            uint32_t Bhf[4][2], Blf[4][2];
#pragma unroll
            for (int jp = 0; jp < 2; ++jp) {
                uint32_t b = smem_u32(&Bs[(wn + h * 32 + jp * 16 + b_row) * SK + k0 + b_col]);
                ldsm_x4(Bhf[2 * jp][0], Bhf[2 * jp][1], Bhf[2 * jp + 1][0], Bhf[2 * jp + 1][1], b);
                uint32_t bl = smem_u32(&Bs[(wn + h * 32 + jp * 16 + b_row) * SK + 32 + k0 + b_col]);
                ldsm_x4(Blf[2 * jp][0], Blf[2 * jp][1], Blf[2 * jp + 1][0], Blf[2 * jp + 1][1], bl);
            }
#pragma unroll
            for (int mt = 0; mt < 4; ++mt)
#pragma unroll
                for (int j = 0; j < 4; ++j) {
                    int nt = h * 4 + j;
                    mma_bf16(acc[mt][nt], Ahf[mt], Bhf[j]);
                    mma_bf16(acc[mt][nt], Ahf[mt], Blf[j]);
                    mma_bf16(acc[mt][nt], Alf[mt], Bhf[j]);
                }
        }
    }
}

// Pipelined K loop over S stages of BKF=32.
__device__ __forceinline__ void gemm_tiles(char* dyn,
    const __nv_bfloat16* Ah, const __nv_bfloat16* Al, int lda, int m0,
    const __nv_bfloat16* Bh, const __nv_bfloat16* Bl, int ldb, int n0,
    int S, float acc[4][8][4], int t, int lane, int wid)
{
    fill_stage(dyn, Ah, Al, lda, m0, Bh, Bl, ldb, n0, 0, t);
    for (int s = 0; s < S; ++s) {
        if (s + 1 < S) {
            fill_stage(dyn + ((s + 1) & 1) * STAGE_BYTES, Ah, Al, lda, m0,
                       Bh, Bl, ldb, n0, (s + 1) * BKF, t);
            CP_WAIT_1();
        } else {
            CP_WAIT_0();
        }
        __syncthreads();
        char* buf = dyn + (s & 1) * STAGE_BYTES;
        compute_stage(reinterpret_cast<const __nv_bfloat16*>(buf),
                      reinterpret_cast<const __nv_bfloat16*>(buf + TILE_HALVES * 2),
                      acc, lane, wid);
        __syncthreads();
    }
}

// ============================================================================
// Kernel 1: fused S + split of query / context into bf16 hi/lo
// ============================================================================
__global__ void k_prep(const float* __restrict__ query, const float* __restrict__ aw)
{
    const int PD4 = P * D / 4;
    int i = blockIdx.x * blockDim.x + threadIdx.x;   // over B*P*D/4
    int b = i / PD4;
    int pd4 = i - b * PD4;
    const float4* q4 = reinterpret_cast<const float4*>(query);
    const float4* a4 = reinterpret_cast<const float4*>(aw);
    float4 q[C];
    float4 S = make_float4(0.f, 0.f, 0.f, 0.f);
#pragma unroll
    for (int c = 0; c < C; ++c) {
        q[c] = q4[((size_t)b * C + c) * PD4 + pd4];
        float4 a = a4[c * PD4 + pd4];
        S.x += a.x * q[c].x; S.y += a.y * q[c].y;
        S.z += a.z * q[c].z; S.w += a.w * q[c].w;
    }
#pragma unroll
    for (int c = 0; c < C; ++c) {
        float4 a = a4[c * PD4 + pd4];
        float cx = S.x - a.x * q[c].x, cy = S.y - a.y * q[c].y;
        float cz = S.z - a.z * q[c].z, cw = S.w - a.w * q[c].w;
        size_t off = (((size_t)b * C + c) * PD4 + pd4) * 4;
        split_store2(g_qh, g_ql, off,     q[c].x, q[c].y);
        split_store2(g_qh, g_ql, off + 2, q[c].z, q[c].w);
        split_store2(g_ch, g_cl, off,     cx, cy);
        split_store2(g_ch, g_cl, off + 2, cz, cw);
    }
}

// ============================================================================
// Kernel 2: weights -> transposed bf16 hi/lo  (W[d][e] -> Wt[e][d])
// ============================================================================
__global__ void k_prep_wt(const float* __restrict__ Wq, const float* __restrict__ Wk,
                          const float* __restrict__ Wv)
{
    const int CDD4 = C * D * D / 4;
    int i = blockIdx.x * blockDim.x + threadIdx.x;
    int which = i / CDD4;
    int j = i - which * CDD4;
    int c = j / (D * D / 4);
    int j2 = j - c * (D * D / 4);
    int k = j2 / (D / 4);
    int n4 = (j2 - k * (D / 4)) * 4;
    const float* W = (which == 0) ? Wq : (which == 1) ? Wk : Wv;
    float4 v = *reinterpret_cast<const float4*>(W + ((size_t)c * D + k) * D + n4);
    float vv[4] = {v.x, v.y, v.z, v.w};
    size_t base = ((size_t)which * C + c) * D * D;
#pragma unroll
    for (int e = 0; e < 4; ++e) {
        __nv_bfloat16 h, l;
        split1(vv[e], h, l);
        g_wth[base + (size_t)(n4 + e) * D + k] = h;
        g_wtl[base + (size_t)(n4 + e) * D + k] = l;
    }
}

// ============================================================================
// Kernel 3: Q/K projections. grid(x=2, y=4, z=bc*2+which), 128 thr
// ============================================================================
__global__ void __launch_bounds__(128) k_projQK(const float* __restrict__ bq,
                                                const float* __restrict__ bk)
{
    extern __shared__ char dyn[];
    int z = blockIdx.z;
    int which = z & 1;
    int bc = z >> 1;
    int c = bc & 15;
    int m0 = blockIdx.y * BM, n0 = blockIdx.x * BN;
    int t = threadIdx.x, lane = t & 31, wid = t >> 5;

    size_t abase = (size_t)bc * P * D;
    const __nv_bfloat16* Ah = (which == 0 ? g_qh : g_ch) + abase;
    const __nv_bfloat16* Al = (which == 0 ? g_ql : g_cl) + abase;
    size_t wbase = ((size_t)which * C + c) * D * D;

    float acc[4][8][4] = {};
    gemm_tiles(dyn, Ah, Al, D, m0, g_wth + wbase, g_wtl + wbase, D, n0,
               D / BKF, acc, t, lane, wid);

    const float* bias = which ? bk : bq;
    float scale = which ? 1.0f : 0.0625f;
    __nv_bfloat16* OH = which ? g_Kh : g_Qh;
    __nv_bfloat16* OL = which ? g_Kl : g_Ql;
    int wm = (wid & 1) * 64, wn = (wid >> 1) * 64;
    int gr = lane >> 2, gc = (lane & 3) * 2;
#pragma unroll
    for (int mt = 0; mt < 4; ++mt)
#pragma unroll
        for (int nt = 0; nt < 8; ++nt) {
            int p0 = m0 + wm + mt * 16 + gr;
            int e0 = n0 + wn + nt * 8 + gc;
            float2 bb = *reinterpret_cast<const float2*>(&bias[c * D + e0]);
            float v0 = fmaxf(acc[mt][nt][0] + bb.x, 0.f) * scale;
            float v1 = fmaxf(acc[mt][nt][1] + bb.y, 0.f) * scale;
            float v2 = fmaxf(acc[mt][nt][2] + bb.x, 0.f) * scale;
            float v3 = fmaxf(acc[mt][nt][3] + bb.y, 0.f) * scale;
            split_store2(OH, OL, abase + (size_t)p0 * D + e0, v0, v1);
            split_store2(OH, OL, abase + (size_t)(p0 + 8) * D + e0, v2, v3);
        }
}

// ============================================================================
// Kernel 4: V^T projection. Vt[e][p] = relu(Wt[e][:]·ctx[p][:] + bv[e])
// grid(x=4 over p, y=2 over e, z=bc), 128 thr
// ============================================================================
__global__ void __launch_bounds__(128) k_projVT(const float* __restrict__ bv)
{
    extern __shared__ char dyn[];
    int bc = blockIdx.z;
    int c = bc & 15;
    int m0 = blockIdx.y * BM;          // e
    int n0 = blockIdx.x * BN;          // p
    int t = threadIdx.x, lane = t & 31, wid = t >> 5;

    size_t cbase = (size_t)bc * P * D;
    size_t wbase = ((size_t)2 * C + c) * D * D;
    float acc[4][8][4] = {};
    gemm_tiles(dyn, g_wth + wbase, g_wtl + wbase, D, m0,
               g_ch + cbase, g_cl + cbase, D, n0, D / BKF, acc, t, lane, wid);

    int wm = (wid & 1) * 64, wn = (wid >> 1) * 64;
    int gr = lane >> 2, gc = (lane & 3) * 2;
    size_t obase = (size_t)bc * D * P;
#pragma unroll
    for (int mt = 0; mt < 4; ++mt)
#pragma unroll
        for (int nt = 0; nt < 8; ++nt) {
            int e0 = m0 + wm + mt * 16 + gr;
            int p0 = n0 + wn + nt * 8 + gc;
            float b0 = bv[c * D + e0], b1 = bv[c * D + e0 + 8];
            float v0 = fmaxf(acc[mt][nt][0] + b0, 0.f);
            float v1 = fmaxf(acc[mt][nt][1] + b0, 0.f);
            float v2 = fmaxf(acc[mt][nt][2] + b1, 0.f);
            float v3 = fmaxf(acc[mt][nt][3] + b1, 0.f);
            split_store2(g_VTh, g_VTl, obase + (size_t)e0 * P + p0, v0, v1);
            split_store2(g_VTh, g_VTl, obase + (size_t)(e0 + 8) * P + p0, v2, v3);
        }
}

// ============================================================================
// Kernel 5: scores = Q @ K^T. grid(x=4, y=4, z=bc), 128 thr
// ============================================================================
__global__ void __launch_bounds__(128) k_scores_m()
{
    extern __shared__ char dyn[];
    int bc = blockIdx.z;
    int m0 = blockIdx.y * BM, n0 = blockIdx.x * BN;
    int t = threadIdx.x, lane = t & 31, wid = t >> 5;
    size_t base = (size_t)bc * P * D;

    float acc[4][8][4] = {};
    gemm_tiles(dyn, g_Qh + base, g_Ql + base, D, m0,
               g_Kh + base, g_Kl + base, D, n0, D / BKF, acc, t, lane, wid);

    int wm = (wid & 1) * 64, wn = (wid >> 1) * 64;
    int gr = lane >> 2, gc = (lane & 3) * 2;
    float* Out = g_At + (size_t)bc * P * P;
#pragma unroll
    for (int mt = 0; mt < 4; ++mt)
#pragma unroll
        for (int nt = 0; nt < 8; ++nt) {
            int p0 = m0 + wm + mt * 16 + gr;
            int q0 = n0 + wn + nt * 8 + gc;
            *reinterpret_cast<float2*>(&Out[(size_t)p0 * P + q0]) =
                make_float2(acc[mt][nt][0], acc[mt][nt][1]);
            *reinterpret_cast<float2*>(&Out[(size_t)(p0 + 8) * P + q0]) =
                make_float2(acc[mt][nt][2], acc[mt][nt][3]);
        }
}

// ============================================================================
// Kernel 6: row softmax (512) + split to bf16 hi/lo
// ============================================================================
__global__ void k_softmax_t()
{
    size_t row = blockIdx.x;
    int t = threadIdx.x;
    const float4* r = reinterpret_cast<const float4*>(g_At + row * P);
    float4 v = r[t];
    float m = fmaxf(fmaxf(v.x, v.y), fmaxf(v.z, v.w));
#pragma unroll
    for (int o = 16; o > 0; o >>= 1) m = fmaxf(m, __shfl_xor_sync(0xffffffffu, m, o));
    __shared__ float sm[4], ss[4];
    int w = t >> 5, lane = t & 31;
    if (lane == 0) sm[w] = m;
    __syncthreads();
    m = fmaxf(fmaxf(sm[0], sm[1]), fmaxf(sm[2], sm[3]));
    v.x = __expf(v.x - m); v.y = __expf(v.y - m);
    v.z = __expf(v.z - m); v.w = __expf(v.w - m);
    float s = v.x + v.y + v.z + v.w;
#pragma unroll
    for (int o = 16; o > 0; o >>= 1) s += __shfl_xor_sync(0xffffffffu, s, o);
    if (lane == 0) ss[w] = s;
    __syncthreads();
    s = ss[0] + ss[1] + ss[2] + ss[3];
    float inv = 1.0f / s;
    size_t off = row * P + (size_t)t * 4;
    split_store2(g_Ah, g_Al, off,     v.x * inv, v.y * inv);
    split_store2(g_Ah, g_Al, off + 2, v.z * inv, v.w * inv);
}

// ============================================================================
// Kernel 7: out = attn @ V (via V^T). grid(x=2 over e, y=4 over p, z=bc)
// ============================================================================
__global__ void __launch_bounds__(128) k_av_m(float* __restrict__ out)
{
    extern __shared__ char dyn[];
    int bc = blockIdx.z;
    int m0 = blockIdx.y * BM;          // p
    int n0 = blockIdx.x * BN;          // e
    int t = threadIdx.x, lane = t & 31, wid = t >> 5;
    size_t abase = (size_t)bc * P * P;
    size_t vbase = (size_t)bc * D * P;

    float acc[4][8][4] = {};
    gemm_tiles(dyn, g_Ah + abase, g_Al + abase, P, m0,
               g_VTh + vbase, g_VTl + vbase, P, n0, P / BKF, acc, t, lane, wid);

    int wm = (wid & 1) * 64, wn = (wid >> 1) * 64;
    int gr = lane >> 2, gc = (lane & 3) * 2;
    float* Ob = out + (size_t)bc * P * D;
#pragma unroll
    for (int mt = 0; mt < 4; ++mt)
#pragma unroll
        for (int nt = 0; nt < 8; ++nt) {
            int p0 = m0 + wm + mt * 16 + gr;
            int e0 = n0 + wn + nt * 8 + gc;
            *reinterpret_cast<float2*>(&Ob[(size_t)p0 * D + e0]) =
                make_float2(acc[mt][nt][0], acc[mt][nt][1]);
            *reinterpret_cast<float2*>(&Ob[(size_t)(p0 + 8) * D + e0]) =
                make_float2(acc[mt][nt][2], acc[mt][nt][3]);
        }
}

// ============================================================================
extern "C" void kernel_launch(void* const* d_in, const int* /*in_sizes*/, int /*n_in*/,
                              void* d_out, int /*out_size*/)
{
    const float* query = (const float*)d_in[0];
    const float* aw    = (const float*)d_in[1];
    const float* Wq    = (const float*)d_in[2];
    const float* Wk    = (const float*)d_in[3];
    const float* Wv    = (const float*)d_in[4];
    const float* bq    = (const float*)d_in[5];
    const float* bk    = (const float*)d_in[6];
    const float* bv    = (const float*)d_in[7];
    float* out = (float*)d_out;

    cudaFuncSetAttribute(k_projQK,  cudaFuncAttributeMaxDynamicSharedMemorySize, DYN_BYTES);
    cudaFuncSetAttribute(k_projVT,  cudaFuncAttributeMaxDynamicSharedMemorySize, DYN_BYTES);
    cudaFuncSetAttribute(k_scores_m,cudaFuncAttributeMaxDynamicSharedMemorySize, DYN_BYTES);
    cudaFuncSetAttribute(k_av_m,    cudaFuncAttributeMaxDynamicSharedMemorySize, DYN_BYTES);

    k_prep<<<(B * P * D / 4) / 256, 256>>>(query, aw);
    k_prep_wt<<<(3 * C * D * D / 4) / 256, 256>>>(Wq, Wk, Wv);
    k_projQK<<<dim3(D / BN, P / BM, B * C * 2), 128, DYN_BYTES>>>(bq, bk);
    k_projVT<<<dim3(P / BN, D / BM, B * C), 128, DYN_BYTES>>>(bv);
    k_scores_m<<<dim3(P / BN, P / BM, B * C), 128, DYN_BYTES>>>();
    k_softmax_t<<<B * C * P, 128>>>();
    k_av_m<<<dim3(D / BN, P / BM, B * C), 128, DYN_BYTES>>>(out);
}